// round 16
// baseline (speedup 1.0000x reference)
#include <cuda_runtime.h>
#include <cuda_bf16.h>
#include <cuda_fp16.h>
#include <cstdint>

#define B_  4
#define C_  256
#define CQ_ 64
#define N_  4096

static const size_t ATTN_ELEMS = (size_t)B_ * N_ * N_;   // 67108864
static const size_t OUT_ELEMS  = (size_t)B_ * C_ * N_;   // 4194304

// ---------------- scratch (__device__ globals) ------------------------------
__device__ __nv_bfloat16 g_qhi [(size_t)B_ * N_ * CQ_];  // (b, n, 64) split bf16
__device__ __nv_bfloat16 g_qlo [(size_t)B_ * N_ * CQ_];
__device__ __nv_bfloat16 g_k1hi[(size_t)B_ * N_ * CQ_];
__device__ __nv_bfloat16 g_k1lo[(size_t)B_ * N_ * CQ_];
__device__ __nv_bfloat16 g_k2hi[(size_t)B_ * N_ * CQ_];
__device__ __nv_bfloat16 g_k2lo[(size_t)B_ * N_ * CQ_];
__device__ __half g_vhf [(size_t)B_ * C_ * N_];            // (b, c, m) fp16
__device__ __half g_vthf[(size_t)B_ * C_ * N_];
// E1 bf16 from qk; overwritten in place by softmax with UNNORMALIZED e (fp16).
__device__ __nv_bfloat16 g_attn16[(size_t)B_ * N_ * N_];   // 128 MB
__device__ __nv_bfloat16 g_E2bf  [(size_t)B_ * N_ * N_];   // E2 bf16 (128 MB)
__device__ float g_S[(size_t)B_ * N_];                     // row sums of e

// ======================= PTX helpers (compute_103-safe) =====================
__device__ __forceinline__ uint32_t smem_u32(const void* p) {
    uint32_t a;
    asm("{ .reg .u64 t; cvta.to.shared.u64 t, %1; cvt.u32.u64 %0, t; }" : "=r"(a) : "l"(p));
    return a;
}
#define CP_ASYNC16(sdst, gsrc) asm volatile("cp.async.cg.shared.global [%0], [%1], 16;" :: "r"(sdst), "l"(gsrc))
#define CP_ASYNC_COMMIT()      asm volatile("cp.async.commit_group;" ::: "memory")
#define CP_ASYNC_WAIT0()       asm volatile("cp.async.wait_group 0;" ::: "memory")
#define CP_ASYNC_WAIT1()       asm volatile("cp.async.wait_group 1;" ::: "memory")
#define CP_ASYNC_WAIT2()       asm volatile("cp.async.wait_group 2;" ::: "memory")

#define LDMATRIX_X4(r0, r1, r2, r3, addr) \
    asm volatile("ldmatrix.sync.aligned.m8n8.x4.shared.b16 {%0,%1,%2,%3}, [%4];" \
        : "=r"(r0), "=r"(r1), "=r"(r2), "=r"(r3) : "r"(addr))

#define MMA_BF16(d, a, b) \
    asm volatile("mma.sync.aligned.m16n8k16.row.col.f32.bf16.bf16.f32 " \
        "{%0,%1,%2,%3}, {%4,%5,%6,%7}, {%8,%9}, {%0,%1,%2,%3};" \
        : "+f"((d)[0]), "+f"((d)[1]), "+f"((d)[2]), "+f"((d)[3]) \
        : "r"((a)[0]), "r"((a)[1]), "r"((a)[2]), "r"((a)[3]), "r"((b)[0]), "r"((b)[1]))

#define MMA_F16(d, a, b) \
    asm volatile("mma.sync.aligned.m16n8k16.row.col.f32.f16.f16.f32 " \
        "{%0,%1,%2,%3}, {%4,%5,%6,%7}, {%8,%9}, {%0,%1,%2,%3};" \
        : "+f"((d)[0]), "+f"((d)[1]), "+f"((d)[2]), "+f"((d)[3]) \
        : "r"((a)[0]), "r"((a)[1]), "r"((a)[2]), "r"((a)[3]), "r"((b)[0]), "r"((b)[1]))

__device__ __forceinline__ float sum_bf2(uint32_t u) {
    float2 f = __bfloat1622float2(*(__nv_bfloat162*)&u);
    return f.x + f.y;
}
__device__ __forceinline__ float2 unpk(uint32_t u) {
    return __bfloat1622float2(*(__nv_bfloat162*)&u);
}

// ---------------------------------------------------------------------------
// Fused q/k1/k2 projection: blockIdx.y selects which projection.
// ---------------------------------------------------------------------------
__global__ void proj_qk3_kernel(const float* __restrict__ Wq,  const float* __restrict__ bq,
                                const float* __restrict__ Wk,  const float* __restrict__ bk,
                                const float* __restrict__ Wk2, const float* __restrict__ bk2,
                                const float* __restrict__ x3,  const float* __restrict__ x1,
                                const float* __restrict__ x2)
{
    __shared__ float Ws[16][68];
    __shared__ float Xs[16][68];
    const int b  = blockIdx.z;
    const int n0 = blockIdx.x * 64;
    const int which = blockIdx.y;
    const int t  = threadIdx.x;
    const int ty = t / 16, tx = t % 16;

    const float *W, *bias, *X;
    __nv_bfloat16 *Yhi, *Ylo;
    if (which == 0)      { W = Wq;  bias = bq;  X = x3; Yhi = g_qhi;  Ylo = g_qlo;  }
    else if (which == 1) { W = Wk;  bias = bk;  X = x1; Yhi = g_k1hi; Ylo = g_k1lo; }
    else                 { W = Wk2; bias = bk2; X = x2; Yhi = g_k2hi; Ylo = g_k2lo; }

    const float* Xb = X + (size_t)b * C_ * N_;

    float acc[4][4] = {};
    for (int k0 = 0; k0 < C_; k0 += 16) {
        {
            int o = t / 4, k4 = (t % 4) * 4;
            float4 w = *(const float4*)&W[(size_t)o * C_ + k0 + k4];
            Ws[k4 + 0][o] = w.x; Ws[k4 + 1][o] = w.y;
            Ws[k4 + 2][o] = w.z; Ws[k4 + 3][o] = w.w;
        }
        {
            int kk = t / 16, n4 = (t % 16) * 4;
            *(float4*)&Xs[kk][n4] = *(const float4*)&Xb[(size_t)(k0 + kk) * N_ + n0 + n4];
        }
        __syncthreads();
#pragma unroll
        for (int kk = 0; kk < 16; kk++) {
            float4 wv = *(const float4*)&Ws[kk][ty * 4];
            float4 xv = *(const float4*)&Xs[kk][tx * 4];
            float wa[4] = {wv.x, wv.y, wv.z, wv.w};
            float xa[4] = {xv.x, xv.y, xv.z, xv.w};
#pragma unroll
            for (int i = 0; i < 4; i++)
#pragma unroll
                for (int j = 0; j < 4; j++)
                    acc[i][j] += wa[i] * xa[j];
        }
        __syncthreads();
    }
    float bv[4];
#pragma unroll
    for (int i = 0; i < 4; i++) bv[i] = bias[ty * 4 + i];
#pragma unroll
    for (int i = 0; i < 4; i++)
#pragma unroll
        for (int j = 0; j < 4; j++) {
            int n = n0 + tx * 4 + j;
            float val = acc[i][j] + bv[i];
            __nv_bfloat16 hi = __float2bfloat16(val);
            float lo = val - __bfloat162float(hi);
            size_t idx = ((size_t)b * N_ + n) * 64 + ty * 4 + i;
            Yhi[idx] = hi;
            Ylo[idx] = __float2bfloat16(lo);
        }
}

// ---------------------------------------------------------------------------
// Fused v/vt projection: blockIdx.z = b + 4 * which.  Y[b][o][n] fp16.
// ---------------------------------------------------------------------------
__global__ void proj_v2_kernel(const float* __restrict__ Wv,  const float* __restrict__ bv_,
                               const float* __restrict__ Wv2, const float* __restrict__ bv2,
                               const float* __restrict__ x3,  const float* __restrict__ xt)
{
    __shared__ float Ws[16][68];
    __shared__ float Xs[16][68];
    const int bz = blockIdx.z;
    const int b  = bz & 3;
    const int which = bz >> 2;
    const int n0 = blockIdx.x * 64;
    const int o0 = blockIdx.y * 64;
    const int t  = threadIdx.x;
    const int ty = t / 16, tx = t % 16;

    const float* W    = which ? Wv2 : Wv;
    const float* bias = which ? bv2 : bv_;
    const float* X    = which ? xt  : x3;
    __half* Y         = which ? g_vthf : g_vhf;

    const float* Xb = X + (size_t)b * C_ * N_;

    float acc[4][4] = {};
    for (int k0 = 0; k0 < C_; k0 += 16) {
        {
            int o = t / 4, k4 = (t % 4) * 4;
            float4 w = *(const float4*)&W[(size_t)(o0 + o) * C_ + k0 + k4];
            Ws[k4 + 0][o] = w.x; Ws[k4 + 1][o] = w.y;
            Ws[k4 + 2][o] = w.z; Ws[k4 + 3][o] = w.w;
        }
        {
            int kk = t / 16, n4 = (t % 16) * 4;
            *(float4*)&Xs[kk][n4] = *(const float4*)&Xb[(size_t)(k0 + kk) * N_ + n0 + n4];
        }
        __syncthreads();
#pragma unroll
        for (int kk = 0; kk < 16; kk++) {
            float4 wv = *(const float4*)&Ws[kk][ty * 4];
            float4 xv = *(const float4*)&Xs[kk][tx * 4];
            float wa[4] = {wv.x, wv.y, wv.z, wv.w};
            float xa[4] = {xv.x, xv.y, xv.z, xv.w};
#pragma unroll
            for (int i = 0; i < 4; i++)
#pragma unroll
                for (int j = 0; j < 4; j++)
                    acc[i][j] += wa[i] * xa[j];
        }
        __syncthreads();
    }
    float bvv[4];
#pragma unroll
    for (int i = 0; i < 4; i++) bvv[i] = bias[o0 + ty * 4 + i];
#pragma unroll
    for (int i = 0; i < 4; i++) {
        int o = o0 + ty * 4 + i;
        size_t idx = ((size_t)b * C_ + o) * N_ + n0 + tx * 4;
        __half2 p0, p1;
        p0.x = __float2half(acc[i][0] + bvv[i]);
        p0.y = __float2half(acc[i][1] + bvv[i]);
        p1.x = __float2half(acc[i][2] + bvv[i]);
        p1.y = __float2half(acc[i][3] + bvv[i]);
        *(__half2*)&Y[idx]     = p0;
        *(__half2*)&Y[idx + 2] = p1;
    }
}

// ---------------------------------------------------------------------------
// QK dual GEMM on mma.sync bf16 with hi/lo split (3 terms), fused exp.
// Per-batch launch (bsel). Epilogue staged via smem -> coalesced st.cs.
// ---------------------------------------------------------------------------
#define QK_QHI_B  0
#define QK_QLO_B  (128 * 144)
#define QK_K1HI_B (256 * 144)
#define QK_K1LO_B (320 * 144)
#define QK_K2HI_B (384 * 144)
#define QK_K2LO_B (448 * 144)
#define QK_SMEM_TOTAL (512 * 144)   // 73728 B

__global__ void __launch_bounds__(256, 2)
qk_mma_kernel(int bsel)
{
    extern __shared__ __align__(16) char smem[];
    const uint32_t sbase = smem_u32(smem);
    const int t = threadIdx.x;
    const int wid = t / 32, lane = t % 32;
    const int wn = wid >> 1, wm = wid & 1;

    const int b  = bsel;
    const int m0 = blockIdx.x * 64;
    const int n0 = blockIdx.y * 128;

    const char* qh  = (const char*)(g_qhi  + ((size_t)b * N_ + n0) * 64);
    const char* ql  = (const char*)(g_qlo  + ((size_t)b * N_ + n0) * 64);
    const char* k1h = (const char*)(g_k1hi + ((size_t)b * N_ + m0) * 64);
    const char* k1l = (const char*)(g_k1lo + ((size_t)b * N_ + m0) * 64);
    const char* k2h = (const char*)(g_k2hi + ((size_t)b * N_ + m0) * 64);
    const char* k2l = (const char*)(g_k2lo + ((size_t)b * N_ + m0) * 64);

#pragma unroll
    for (int it = 0; it < 4; it++) {
        int idx = t + 256 * it;
        int row = idx >> 3, q = idx & 7;
        uint32_t d = sbase + (uint32_t)(row * 144 + q * 16);
        int srco = row * 128 + q * 16;
        CP_ASYNC16(d + QK_QHI_B, qh + srco);
        CP_ASYNC16(d + QK_QLO_B, ql + srco);
    }
#pragma unroll
    for (int it = 0; it < 2; it++) {
        int idx = t + 256 * it;
        int row = idx >> 3, q = idx & 7;
        uint32_t d = sbase + (uint32_t)(row * 144 + q * 16);
        int srco = row * 128 + q * 16;
        CP_ASYNC16(d + QK_K1HI_B, k1h + srco);
        CP_ASYNC16(d + QK_K1LO_B, k1l + srco);
        CP_ASYNC16(d + QK_K2HI_B, k2h + srco);
        CP_ASYNC16(d + QK_K2LO_B, k2l + srco);
    }
    CP_ASYNC_COMMIT();
    CP_ASYNC_WAIT0();
    __syncthreads();

    const int g    = lane >> 3;
    const int arow = wn * 32 + ((g & 1) ? 8 : 0) + (lane & 7);
    const int koff = (g >> 1) * 8;
    const int brow = wm * 32 + ((g & 1) ? 8 : 0) + (lane & 7);

    float acc1[2][4][4] = {}, acc2[2][4][4] = {};

#pragma unroll
    for (int kk = 0; kk < 4; kk++) {
        uint32_t ah[2][4], al[2][4];
#pragma unroll
        for (int mi = 0; mi < 2; mi++) {
            uint32_t ka = (uint32_t)((arow + mi * 16) * 144 + (kk * 16 + koff) * 2);
            LDMATRIX_X4(ah[mi][0], ah[mi][1], ah[mi][2], ah[mi][3], sbase + QK_QHI_B + ka);
            LDMATRIX_X4(al[mi][0], al[mi][1], al[mi][2], al[mi][3], sbase + QK_QLO_B + ka);
        }
#pragma unroll
        for (int j2 = 0; j2 < 2; j2++) {
            uint32_t kb = (uint32_t)((brow + j2 * 16) * 144 + (kk * 16 + koff) * 2);
            uint32_t b1h[2][2], b1l[2][2], b2h[2][2], b2l[2][2];
            {
                uint32_t r0, r1, r2, r3;
                LDMATRIX_X4(r0, r1, r2, r3, sbase + QK_K1HI_B + kb);
                b1h[0][0] = r0; b1h[0][1] = r2; b1h[1][0] = r1; b1h[1][1] = r3;
                LDMATRIX_X4(r0, r1, r2, r3, sbase + QK_K1LO_B + kb);
                b1l[0][0] = r0; b1l[0][1] = r2; b1l[1][0] = r1; b1l[1][1] = r3;
                LDMATRIX_X4(r0, r1, r2, r3, sbase + QK_K2HI_B + kb);
                b2h[0][0] = r0; b2h[0][1] = r2; b2h[1][0] = r1; b2h[1][1] = r3;
                LDMATRIX_X4(r0, r1, r2, r3, sbase + QK_K2LO_B + kb);
                b2l[0][0] = r0; b2l[0][1] = r2; b2l[1][0] = r1; b2l[1][1] = r3;
            }
#pragma unroll
            for (int mi = 0; mi < 2; mi++)
#pragma unroll
                for (int jj = 0; jj < 2; jj++) {
                    int j = j2 * 2 + jj;
                    MMA_BF16(acc1[mi][j], ah[mi], b1h[jj]);
                    MMA_BF16(acc1[mi][j], ah[mi], b1l[jj]);
                    MMA_BF16(acc1[mi][j], al[mi], b1h[jj]);
                    MMA_BF16(acc2[mi][j], ah[mi], b2h[jj]);
                    MMA_BF16(acc2[mi][j], ah[mi], b2l[jj]);
                    MMA_BF16(acc2[mi][j], al[mi], b2h[jj]);
                }
        }
    }

    // ---- epilogue: exp -> smem tiles (reuse Q/K space) -> coalesced st.cs ----
    __syncthreads();
    const int gid = lane >> 2, tig = lane & 3;
#pragma unroll
    for (int mi = 0; mi < 2; mi++)
#pragma unroll
        for (int rr = 0; rr < 2; rr++) {
            int nl = wn * 32 + mi * 16 + gid + rr * 8;
#pragma unroll
            for (int j = 0; j < 4; j++) {
                int ml = wm * 32 + j * 8 + tig * 2;
                __nv_bfloat162 e1p, e2p;
                e1p.x = __float2bfloat16(__expf(acc1[mi][j][rr * 2 + 0]));
                e1p.y = __float2bfloat16(__expf(acc1[mi][j][rr * 2 + 1]));
                e2p.x = __float2bfloat16(__expf(acc2[mi][j][rr * 2 + 0]));
                e2p.y = __float2bfloat16(__expf(acc2[mi][j][rr * 2 + 1]));
                *(__nv_bfloat162*)(smem + nl * 144 + ml * 2)              = e1p;
                *(__nv_bfloat162*)(smem + 128 * 144 + nl * 144 + ml * 2)  = e2p;
            }
        }
    __syncthreads();

#pragma unroll
    for (int it = 0; it < 4; it++) {
        int idx = t + 256 * it;
        int r = idx >> 3, q = idx & 7;
        size_t goff = ((size_t)b * N_ + n0 + r) * N_ + m0 + q * 8;
        float4 v1 = *(const float4*)(smem + r * 144 + q * 16);
        __stcs((float4*)&g_attn16[goff], v1);
        float4 v2 = *(const float4*)(smem + 128 * 144 + r * 144 + q * 16);
        __stcs((float4*)&g_E2bf[goff], v2);
    }
}

// ---------------------------------------------------------------------------
// Double softmax (per-batch, bsel), registers + shuffle reductions.
// Writes unnormalized e (fp16) in place + S -> g_S.
// ---------------------------------------------------------------------------
__global__ void __launch_bounds__(256)
softmax2_kernel(int bsel)
{
    __shared__ float2 redw[8];
    __shared__ float2 bc;
    __shared__ float redS[8];
    const int b = bsel, n = blockIdx.x, t = threadIdx.x;
    const int wid = t >> 5, lane = t & 31;
    __nv_bfloat16* rowe1 = g_attn16 + ((size_t)b * N_ + n) * N_;
    const __nv_bfloat16* rowe2 = g_E2bf + ((size_t)b * N_ + n) * N_;

    const uint4* e1v = (const uint4*)rowe1;
    const uint4* e2v = (const uint4*)rowe2;

    uint4 a0 = __ldcs(&e1v[t]);
    uint4 a1 = __ldcs(&e1v[t + 256]);
    uint4 c0 = __ldcs(&e2v[t]);
    uint4 c1 = __ldcs(&e2v[t + 256]);
    float s1 = sum_bf2(a0.x) + sum_bf2(a0.y) + sum_bf2(a0.z) + sum_bf2(a0.w)
             + sum_bf2(a1.x) + sum_bf2(a1.y) + sum_bf2(a1.z) + sum_bf2(a1.w);
    float s2 = sum_bf2(c0.x) + sum_bf2(c0.y) + sum_bf2(c0.z) + sum_bf2(c0.w)
             + sum_bf2(c1.x) + sum_bf2(c1.y) + sum_bf2(c1.z) + sum_bf2(c1.w);

#pragma unroll
    for (int off = 16; off > 0; off >>= 1) {
        s1 += __shfl_xor_sync(0xffffffff, s1, off);
        s2 += __shfl_xor_sync(0xffffffff, s2, off);
    }
    if (lane == 0) redw[wid] = make_float2(s1, s2);
    __syncthreads();
    if (wid == 0) {
        float2 v = (lane < 8) ? redw[lane] : make_float2(0.f, 0.f);
#pragma unroll
        for (int off = 4; off > 0; off >>= 1) {
            v.x += __shfl_xor_sync(0xffffffff, v.x, off);
            v.y += __shfl_xor_sync(0xffffffff, v.y, off);
        }
        if (lane == 0) bc = v;
    }
    __syncthreads();
    const float i1 = 1.f / bc.x, i2 = 1.f / bc.y;

    float e[16];
    {
        float2 fa, fc;
        fa = unpk(a0.x); fc = unpk(c0.x);
        e[0] = __expf(fa.x * i1 + fc.x * i2);  e[1] = __expf(fa.y * i1 + fc.y * i2);
        fa = unpk(a0.y); fc = unpk(c0.y);
        e[2] = __expf(fa.x * i1 + fc.x * i2);  e[3] = __expf(fa.y * i1 + fc.y * i2);
        fa = unpk(a0.z); fc = unpk(c0.z);
        e[4] = __expf(fa.x * i1 + fc.x * i2);  e[5] = __expf(fa.y * i1 + fc.y * i2);
        fa = unpk(a0.w); fc = unpk(c0.w);
        e[6] = __expf(fa.x * i1 + fc.x * i2);  e[7] = __expf(fa.y * i1 + fc.y * i2);
        fa = unpk(a1.x); fc = unpk(c1.x);
        e[8] = __expf(fa.x * i1 + fc.x * i2);  e[9] = __expf(fa.y * i1 + fc.y * i2);
        fa = unpk(a1.y); fc = unpk(c1.y);
        e[10] = __expf(fa.x * i1 + fc.x * i2); e[11] = __expf(fa.y * i1 + fc.y * i2);
        fa = unpk(a1.z); fc = unpk(c1.z);
        e[12] = __expf(fa.x * i1 + fc.x * i2); e[13] = __expf(fa.y * i1 + fc.y * i2);
        fa = unpk(a1.w); fc = unpk(c1.w);
        e[14] = __expf(fa.x * i1 + fc.x * i2); e[15] = __expf(fa.y * i1 + fc.y * i2);
    }
    uint4 pk;
    __half2 p;
    p.x = __float2half(e[0]);  p.y = __float2half(e[1]);  pk.x = *(uint32_t*)&p;
    p.x = __float2half(e[2]);  p.y = __float2half(e[3]);  pk.y = *(uint32_t*)&p;
    p.x = __float2half(e[4]);  p.y = __float2half(e[5]);  pk.z = *(uint32_t*)&p;
    p.x = __float2half(e[6]);  p.y = __float2half(e[7]);  pk.w = *(uint32_t*)&p;
    ((uint4*)rowe1)[t] = pk;
    p.x = __float2half(e[8]);  p.y = __float2half(e[9]);  pk.x = *(uint32_t*)&p;
    p.x = __float2half(e[10]); p.y = __float2half(e[11]); pk.y = *(uint32_t*)&p;
    p.x = __float2half(e[12]); p.y = __float2half(e[13]); pk.z = *(uint32_t*)&p;
    p.x = __float2half(e[14]); p.y = __float2half(e[15]); pk.w = *(uint32_t*)&p;
    ((uint4*)rowe1)[t + 256] = pk;

    float s = 0.f;
#pragma unroll
    for (int i = 0; i < 16; i++) s += e[i];
#pragma unroll
    for (int off = 16; off > 0; off >>= 1)
        s += __shfl_xor_sync(0xffffffff, s, off);
    if (lane == 0) redS[wid] = s;
    __syncthreads();
    if (wid == 0) {
        float v = (lane < 8) ? redS[lane] : 0.f;
#pragma unroll
        for (int off = 4; off > 0; off >>= 1)
            v += __shfl_xor_sync(0xffffffff, v, off);
        if (lane == 0) g_S[(size_t)b * N_ + n] = v;
    }
}

// ---------------------------------------------------------------------------
// Expand: fp16 e -> fp32 attn = e / S[row]. Runs concurrent with AV.
// ---------------------------------------------------------------------------
__global__ void expand_kernel(float* __restrict__ attn)
{
    const int b = blockIdx.y, n = blockIdx.x, t = threadIdx.x;
    const __half* rowh = (const __half*)(g_attn16 + ((size_t)b * N_ + n) * N_);
    float* rowf = attn + ((size_t)b * N_ + n) * N_;
    const float ds = 1.f / g_S[(size_t)b * N_ + n];
#pragma unroll
    for (int i = 0; i < 2; i++) {
        int ci = t + 256 * i;
        uint4 h = __ldcs(&((const uint4*)rowh)[ci]);
        float2 f0 = __half22float2(*(__half2*)&h.x);
        float2 f1 = __half22float2(*(__half2*)&h.y);
        float2 f2 = __half22float2(*(__half2*)&h.z);
        float2 f3 = __half22float2(*(__half2*)&h.w);
        float4 o0, o1;
        o0.x = f0.x * ds; o0.y = f0.y * ds; o0.z = f1.x * ds; o0.w = f1.y * ds;
        o1.x = f2.x * ds; o1.y = f2.y * ds; o1.z = f3.x * ds; o1.w = f3.y * ds;
        __stcs((float4*)&rowf[ci * 8],     o0);
        __stcs((float4*)&rowf[ci * 8 + 4], o1);
    }
}

// ---------------------------------------------------------------------------
// AV dual GEMM on mma.sync fp16 over unnormalized e; epilogue applies
// gamma * acc / S[n] + x residual. 128c x 128n, 512 thr, 3-stage cp.async.
// ---------------------------------------------------------------------------
#define AV_VOFF_B   0
#define AV_WOFF_B   (128 * 144)
#define AV_AOFF_B   (256 * 144)
#define AV_STAGE_B  (384 * 144)          // 55296 B per stage
#define AV_SMEM_TOTAL (3 * AV_STAGE_B)   // 165888 B

__device__ __forceinline__ void av_issue(uint32_t sb, const __half* gv,
                                         const __half* gw, const __half* ga,
                                         int m0, int t)
{
#pragma unroll
    for (int it = 0; it < 2; it++) {
        int idx = t + 512 * it;
        int row = idx >> 3, q = idx & 7;
        uint32_t d = sb + (uint32_t)(row * 144 + q * 16);
        CP_ASYNC16(d + AV_VOFF_B, (const char*)(gv + (size_t)row * N_ + m0) + q * 16);
        CP_ASYNC16(d + AV_WOFF_B, (const char*)(gw + (size_t)row * N_ + m0) + q * 16);
        CP_ASYNC16(d + AV_AOFF_B, (const char*)(ga + (size_t)row * N_ + m0) + q * 16);
    }
}

__global__ void __launch_bounds__(512, 1)
av_mma_kernel(const float* __restrict__ x3, const float* __restrict__ xt,
              const float* __restrict__ gma, const float* __restrict__ gma2,
              float* __restrict__ out1, float* __restrict__ out2)
{
    extern __shared__ __align__(16) char smem[];
    const uint32_t sbase = smem_u32(smem);
    const int t = threadIdx.x;
    const int wid = t / 32, lane = t % 32;
    const int wc = wid >> 2, wn = wid & 3;

    const int b  = blockIdx.z;
    const int c0 = blockIdx.y * 128;
    const int n0 = blockIdx.x * 128;

    const __half* vb = g_vhf  + ((size_t)b * C_ + c0) * N_;
    const __half* wb = g_vthf + ((size_t)b * C_ + c0) * N_;
    const __half* ab = (const __half*)g_attn16 + ((size_t)b * N_ + n0) * N_;

    float acc1[2][4][4] = {}, acc2[2][4][4] = {};

    const int g      = lane >> 3;
    const int arow   = wc * 32 + ((g & 1) ? 8 : 0) + (lane & 7);
    const int akoff  = (g >> 1) * 8;
    const int brow   = wn * 32 + ((g & 1) ? 8 : 0) + (lane & 7);
    const int bkoff  = (g >> 1) * 8;

    av_issue(sbase + 0 * AV_STAGE_B, vb, wb, ab, 0,  t); CP_ASYNC_COMMIT();
    av_issue(sbase + 1 * AV_STAGE_B, vb, wb, ab, 64, t); CP_ASYNC_COMMIT();

    int stage = 0;
    for (int i = 0; i < 64; i++) {
        if (i + 2 < 64) {
            int s2 = stage + 2; if (s2 >= 3) s2 -= 3;
            av_issue(sbase + s2 * AV_STAGE_B, vb, wb, ab, (i + 2) * 64, t);
            CP_ASYNC_COMMIT();
            CP_ASYNC_WAIT2();
        } else if (i + 1 < 64) {
            CP_ASYNC_WAIT1();
        } else {
            CP_ASYNC_WAIT0();
        }
        __syncthreads();

        const uint32_t st = sbase + stage * AV_STAGE_B;
#pragma unroll
        for (int kk = 0; kk < 4; kk++) {
            uint32_t av[2][4], aw[2][4], bfr[4][2];
#pragma unroll
            for (int mi = 0; mi < 2; mi++) {
                uint32_t roff = (uint32_t)((arow + mi * 16) * 144 + (kk * 16 + akoff) * 2);
                LDMATRIX_X4(av[mi][0], av[mi][1], av[mi][2], av[mi][3], st + AV_VOFF_B + roff);
                LDMATRIX_X4(aw[mi][0], aw[mi][1], aw[mi][2], aw[mi][3], st + AV_WOFF_B + roff);
            }
#pragma unroll
            for (int j2 = 0; j2 < 2; j2++) {
                uint32_t r0, r1, r2, r3;
                uint32_t baddr = st + AV_AOFF_B +
                    (uint32_t)((brow + j2 * 16) * 144 + (kk * 16 + bkoff) * 2);
                LDMATRIX_X4(r0, r1, r2, r3, baddr);
                bfr[j2 * 2 + 0][0] = r0; bfr[j2 * 2 + 0][1] = r2;
                bfr[j2 * 2 + 1][0] = r1; bfr[j2 * 2 + 1][1] = r3;
            }
#pragma unroll
            for (int mi = 0; mi < 2; mi++)
#pragma unroll
                for (int j = 0; j < 4; j++) {
                    MMA_F16(acc1[mi][j], av[mi], bfr[j]);
                    MMA_F16(acc2[mi][j], aw[mi], bfr[j]);
                }
        }
        __syncthreads();
        if (++stage == 3) stage = 0;
    }

    const float gv1 = gma[0], gv2 = gma2[0];
    const float* Sb = g_S + (size_t)b * N_;
    const int gid = lane >> 2, tig = lane & 3;
#pragma unroll
    for (int mi = 0; mi < 2; mi++) {
#pragma unroll
        for (int rr = 0; rr < 2; rr++) {
            int c = c0 + wc * 32 + mi * 16 + gid + rr * 8;
            size_t rowoff = ((size_t)b * C_ + c) * N_;
#pragma unroll
            for (int j = 0; j < 4; j++) {
                int n = n0 + wn * 32 + j * 8 + tig * 2;
                float2 Sv = *(const float2*)&Sb[n];
                float r1s = gv1 / Sv.x, r1s2 = gv1 / Sv.y;
                float r2s = gv2 / Sv.x, r2s2 = gv2 / Sv.y;
                float2 xv = *(const float2*)&x3[rowoff + n];
                float2 o1;
                o1.x = r1s  * acc1[mi][j][rr * 2 + 0] + xv.x;
                o1.y = r1s2 * acc1[mi][j][rr * 2 + 1] + xv.y;
                *(float2*)&out1[rowoff + n] = o1;
                float2 xtv = *(const float2*)&xt[rowoff + n];
                float2 o2;
                o2.x = r2s  * acc2[mi][j][rr * 2 + 0] + xtv.x;
                o2.y = r2s2 * acc2[mi][j][rr * 2 + 1] + xtv.y;
                *(float2*)&out2[rowoff + n] = o2;
            }
        }
    }
}

// ---------------------------------------------------------------------------
extern "C" void kernel_launch(void* const* d_in, const int* in_sizes, int n_in,
                              void* d_out, int out_size)
{
    const float* x1  = (const float*)d_in[0];
    const float* x2  = (const float*)d_in[1];
    const float* x3  = (const float*)d_in[2];
    const float* xt  = (const float*)d_in[3];
    const float* Wq  = (const float*)d_in[4];
    const float* bq  = (const float*)d_in[5];
    const float* Wk  = (const float*)d_in[6];
    const float* bk  = (const float*)d_in[7];
    const float* Wk2 = (const float*)d_in[8];
    const float* bk2 = (const float*)d_in[9];
    const float* Wv  = (const float*)d_in[10];
    const float* bv  = (const float*)d_in[11];
    const float* Wv2 = (const float*)d_in[12];
    const float* bv2 = (const float*)d_in[13];
    const float* gamma  = (const float*)d_in[14];
    const float* gamma2 = (const float*)d_in[15];

    float* attn = (float*)d_out;
    float* out1 = attn + ATTN_ELEMS;
    float* out2 = out1 + OUT_ELEMS;

    // Streams/events created once (host-side resources only).
    static cudaStream_t sv = nullptr;   // side stream: proj_v, then expand
    static cudaStream_t ss = nullptr;   // softmax stream
    static cudaEvent_t ev_fork = nullptr, ev_vdone = nullptr;
    static cudaEvent_t ev_qk[B_] = {}, ev_smlast = nullptr, ev_expdone = nullptr;
    if (sv == nullptr) {
        cudaStreamCreateWithFlags(&sv, cudaStreamNonBlocking);
        cudaStreamCreateWithFlags(&ss, cudaStreamNonBlocking);
        cudaEventCreateWithFlags(&ev_fork, cudaEventDisableTiming);
        cudaEventCreateWithFlags(&ev_vdone, cudaEventDisableTiming);
        cudaEventCreateWithFlags(&ev_smlast, cudaEventDisableTiming);
        cudaEventCreateWithFlags(&ev_expdone, cudaEventDisableTiming);
        for (int b = 0; b < B_; b++)
            cudaEventCreateWithFlags(&ev_qk[b], cudaEventDisableTiming);
    }

    dim3 blk(256);

    // fork: v/vt projections on side stream (needed only by AV)
    cudaEventRecord(ev_fork, 0);
    cudaStreamWaitEvent(sv, ev_fork, 0);
    cudaStreamWaitEvent(ss, ev_fork, 0);
    proj_v2_kernel<<<dim3(N_ / 64, C_ / 64, 2 * B_), blk, 0, sv>>>(Wv, bv, Wv2, bv2, x3, xt);
    cudaEventRecord(ev_vdone, sv);

    // main chain: fused q/k projections
    proj_qk3_kernel<<<dim3(N_ / 64, 3, B_), blk>>>(Wq, bq, Wk, bk, Wk2, bk2, x3, x1, x2);

    // per-batch qk (main, tensor-bound) pipelined with softmax (ss, DRAM-bound)
    cudaFuncSetAttribute(qk_mma_kernel, cudaFuncAttributeMaxDynamicSharedMemorySize, QK_SMEM_TOTAL);
    for (int b = 0; b < B_; b++) {
        qk_mma_kernel<<<dim3(N_ / 64, N_ / 128, 1), blk, QK_SMEM_TOTAL>>>(b);
        cudaEventRecord(ev_qk[b], 0);
        cudaStreamWaitEvent(ss, ev_qk[b], 0);
        softmax2_kernel<<<dim3(N_, 1), blk, 0, ss>>>(b);
    }
    cudaEventRecord(ev_smlast, ss);

    // expand fp32 attn on side stream, concurrent with AV
    cudaStreamWaitEvent(sv, ev_smlast, 0);
    expand_kernel<<<dim3(N_, B_), blk, 0, sv>>>(attn);
    cudaEventRecord(ev_expdone, sv);

    // AV on main stream (needs all softmax output + v/vt)
    cudaStreamWaitEvent(0, ev_smlast, 0);
    cudaStreamWaitEvent(0, ev_vdone, 0);
    cudaFuncSetAttribute(av_mma_kernel, cudaFuncAttributeMaxDynamicSharedMemorySize, AV_SMEM_TOTAL);
    av_mma_kernel<<<dim3(N_ / 128, C_ / 128, B_), dim3(512), AV_SMEM_TOTAL>>>(
        x3, xt, gamma, gamma2, out1, out2);

    // rejoin: expand must be ordered before capture end
    cudaStreamWaitEvent(0, ev_expdone, 0);
}

// round 17
// speedup vs baseline: 1.0888x; 1.0888x over previous
#include <cuda_runtime.h>
#include <cuda_bf16.h>
#include <cuda_fp16.h>
#include <cstdint>

#define B_  4
#define C_  256
#define CQ_ 64
#define N_  4096

static const size_t ATTN_ELEMS = (size_t)B_ * N_ * N_;   // 67108864
static const size_t OUT_ELEMS  = (size_t)B_ * C_ * N_;   // 4194304

// ---------------- scratch (__device__ globals) ------------------------------
__device__ __half g_q16hi[(size_t)B_ * N_ * CQ_];   // q split fp16 (exact in q)
__device__ __half g_q16lo[(size_t)B_ * N_ * CQ_];
__device__ __half g_k116 [(size_t)B_ * N_ * CQ_];   // k1, k2 single fp16
__device__ __half g_k216 [(size_t)B_ * N_ * CQ_];
__device__ __half g_vhf [(size_t)B_ * C_ * N_];     // (b, c, m) fp16
__device__ __half g_vthf[(size_t)B_ * C_ * N_];
// E1 bf16 from qk; overwritten in place by softmax with UNNORMALIZED e (fp16).
__device__ __nv_bfloat16 g_attn16[(size_t)B_ * N_ * N_];   // 128 MB
__device__ __nv_bfloat16 g_E2bf  [(size_t)B_ * N_ * N_];   // E2 bf16 (128 MB)
__device__ float g_S[(size_t)B_ * N_];                     // row sums of e

// ======================= PTX helpers (compute_103-safe) =====================
__device__ __forceinline__ uint32_t smem_u32(const void* p) {
    uint32_t a;
    asm("{ .reg .u64 t; cvta.to.shared.u64 t, %1; cvt.u32.u64 %0, t; }" : "=r"(a) : "l"(p));
    return a;
}
#define CP_ASYNC16(sdst, gsrc) asm volatile("cp.async.cg.shared.global [%0], [%1], 16;" :: "r"(sdst), "l"(gsrc))
#define CP_ASYNC_COMMIT()      asm volatile("cp.async.commit_group;" ::: "memory")
#define CP_ASYNC_WAIT0()       asm volatile("cp.async.wait_group 0;" ::: "memory")
#define CP_ASYNC_WAIT1()       asm volatile("cp.async.wait_group 1;" ::: "memory")
#define CP_ASYNC_WAIT2()       asm volatile("cp.async.wait_group 2;" ::: "memory")

#define LDMATRIX_X4(r0, r1, r2, r3, addr) \
    asm volatile("ldmatrix.sync.aligned.m8n8.x4.shared.b16 {%0,%1,%2,%3}, [%4];" \
        : "=r"(r0), "=r"(r1), "=r"(r2), "=r"(r3) : "r"(addr))

#define MMA_F16(d, a, b) \
    asm volatile("mma.sync.aligned.m16n8k16.row.col.f32.f16.f16.f32 " \
        "{%0,%1,%2,%3}, {%4,%5,%6,%7}, {%8,%9}, {%0,%1,%2,%3};" \
        : "+f"((d)[0]), "+f"((d)[1]), "+f"((d)[2]), "+f"((d)[3]) \
        : "r"((a)[0]), "r"((a)[1]), "r"((a)[2]), "r"((a)[3]), "r"((b)[0]), "r"((b)[1]))

__device__ __forceinline__ float sum_bf2(uint32_t u) {
    float2 f = __bfloat1622float2(*(__nv_bfloat162*)&u);
    return f.x + f.y;
}
__device__ __forceinline__ float2 unpk(uint32_t u) {
    return __bfloat1622float2(*(__nv_bfloat162*)&u);
}

// ---------------------------------------------------------------------------
// Fused q/k1/k2 projection: blockIdx.y selects which projection.
// q -> fp16 hi/lo split (exact); k1/k2 -> single fp16.
// ---------------------------------------------------------------------------
__global__ void proj_qk3_kernel(const float* __restrict__ Wq,  const float* __restrict__ bq,
                                const float* __restrict__ Wk,  const float* __restrict__ bk,
                                const float* __restrict__ Wk2, const float* __restrict__ bk2,
                                const float* __restrict__ x3,  const float* __restrict__ x1,
                                const float* __restrict__ x2)
{
    __shared__ float Ws[16][68];
    __shared__ float Xs[16][68];
    const int b  = blockIdx.z;
    const int n0 = blockIdx.x * 64;
    const int which = blockIdx.y;
    const int t  = threadIdx.x;
    const int ty = t / 16, tx = t % 16;

    const float *W, *bias, *X;
    if (which == 0)      { W = Wq;  bias = bq;  X = x3; }
    else if (which == 1) { W = Wk;  bias = bk;  X = x1; }
    else                 { W = Wk2; bias = bk2; X = x2; }

    const float* Xb = X + (size_t)b * C_ * N_;

    float acc[4][4] = {};
    for (int k0 = 0; k0 < C_; k0 += 16) {
        {
            int o = t / 4, k4 = (t % 4) * 4;
            float4 w = *(const float4*)&W[(size_t)o * C_ + k0 + k4];
            Ws[k4 + 0][o] = w.x; Ws[k4 + 1][o] = w.y;
            Ws[k4 + 2][o] = w.z; Ws[k4 + 3][o] = w.w;
        }
        {
            int kk = t / 16, n4 = (t % 16) * 4;
            *(float4*)&Xs[kk][n4] = *(const float4*)&Xb[(size_t)(k0 + kk) * N_ + n0 + n4];
        }
        __syncthreads();
#pragma unroll
        for (int kk = 0; kk < 16; kk++) {
            float4 wv = *(const float4*)&Ws[kk][ty * 4];
            float4 xv = *(const float4*)&Xs[kk][tx * 4];
            float wa[4] = {wv.x, wv.y, wv.z, wv.w};
            float xa[4] = {xv.x, xv.y, xv.z, xv.w};
#pragma unroll
            for (int i = 0; i < 4; i++)
#pragma unroll
                for (int j = 0; j < 4; j++)
                    acc[i][j] += wa[i] * xa[j];
        }
        __syncthreads();
    }
    float bv[4];
#pragma unroll
    for (int i = 0; i < 4; i++) bv[i] = bias[ty * 4 + i];
#pragma unroll
    for (int i = 0; i < 4; i++)
#pragma unroll
        for (int j = 0; j < 4; j++) {
            int n = n0 + tx * 4 + j;
            float val = acc[i][j] + bv[i];
            size_t idx = ((size_t)b * N_ + n) * 64 + ty * 4 + i;
            if (which == 0) {
                __half hi = __float2half(val);
                g_q16hi[idx] = hi;
                g_q16lo[idx] = __float2half(val - __half2float(hi));
            } else if (which == 1) {
                g_k116[idx] = __float2half(val);
            } else {
                g_k216[idx] = __float2half(val);
            }
        }
}

// ---------------------------------------------------------------------------
// Fused v/vt projection: blockIdx.z = b + 4 * which.  Y[b][o][n] fp16.
// ---------------------------------------------------------------------------
__global__ void proj_v2_kernel(const float* __restrict__ Wv,  const float* __restrict__ bv_,
                               const float* __restrict__ Wv2, const float* __restrict__ bv2,
                               const float* __restrict__ x3,  const float* __restrict__ xt)
{
    __shared__ float Ws[16][68];
    __shared__ float Xs[16][68];
    const int bz = blockIdx.z;
    const int b  = bz & 3;
    const int which = bz >> 2;
    const int n0 = blockIdx.x * 64;
    const int o0 = blockIdx.y * 64;
    const int t  = threadIdx.x;
    const int ty = t / 16, tx = t % 16;

    const float* W    = which ? Wv2 : Wv;
    const float* bias = which ? bv2 : bv_;
    const float* X    = which ? xt  : x3;
    __half* Y         = which ? g_vthf : g_vhf;

    const float* Xb = X + (size_t)b * C_ * N_;

    float acc[4][4] = {};
    for (int k0 = 0; k0 < C_; k0 += 16) {
        {
            int o = t / 4, k4 = (t % 4) * 4;
            float4 w = *(const float4*)&W[(size_t)(o0 + o) * C_ + k0 + k4];
            Ws[k4 + 0][o] = w.x; Ws[k4 + 1][o] = w.y;
            Ws[k4 + 2][o] = w.z; Ws[k4 + 3][o] = w.w;
        }
        {
            int kk = t / 16, n4 = (t % 16) * 4;
            *(float4*)&Xs[kk][n4] = *(const float4*)&Xb[(size_t)(k0 + kk) * N_ + n0 + n4];
        }
        __syncthreads();
#pragma unroll
        for (int kk = 0; kk < 16; kk++) {
            float4 wv = *(const float4*)&Ws[kk][ty * 4];
            float4 xv = *(const float4*)&Xs[kk][tx * 4];
            float wa[4] = {wv.x, wv.y, wv.z, wv.w};
            float xa[4] = {xv.x, xv.y, xv.z, xv.w};
#pragma unroll
            for (int i = 0; i < 4; i++)
#pragma unroll
                for (int j = 0; j < 4; j++)
                    acc[i][j] += wa[i] * xa[j];
        }
        __syncthreads();
    }
    float bvv[4];
#pragma unroll
    for (int i = 0; i < 4; i++) bvv[i] = bias[o0 + ty * 4 + i];
#pragma unroll
    for (int i = 0; i < 4; i++) {
        int o = o0 + ty * 4 + i;
        size_t idx = ((size_t)b * C_ + o) * N_ + n0 + tx * 4;
        __half2 p0, p1;
        p0.x = __float2half(acc[i][0] + bvv[i]);
        p0.y = __float2half(acc[i][1] + bvv[i]);
        p1.x = __float2half(acc[i][2] + bvv[i]);
        p1.y = __float2half(acc[i][3] + bvv[i]);
        *(__half2*)&Y[idx]     = p0;
        *(__half2*)&Y[idx + 2] = p1;
    }
}

// ---------------------------------------------------------------------------
// QK dual GEMM on mma.sync fp16, 2-term split: z = qhi.k + qlo.k (exact in q).
// Fused exp epilogue staged via smem -> coalesced streaming stores. Grid z=B.
// ---------------------------------------------------------------------------
#define QK_QHI_B  0
#define QK_QLO_B  (128 * 144)
#define QK_K1_B   (256 * 144)
#define QK_K2_B   (320 * 144)
#define QK_SMEM_TOTAL (384 * 144)   // 55296 B

__global__ void __launch_bounds__(256, 2)
qk_mma_kernel()
{
    extern __shared__ __align__(16) char smem[];
    const uint32_t sbase = smem_u32(smem);
    const int t = threadIdx.x;
    const int wid = t / 32, lane = t % 32;
    const int wn = wid >> 1, wm = wid & 1;

    const int b  = blockIdx.z;
    const int m0 = blockIdx.x * 64;
    const int n0 = blockIdx.y * 128;

    const char* qh = (const char*)(g_q16hi + ((size_t)b * N_ + n0) * 64);
    const char* ql = (const char*)(g_q16lo + ((size_t)b * N_ + n0) * 64);
    const char* k1 = (const char*)(g_k116  + ((size_t)b * N_ + m0) * 64);
    const char* k2 = (const char*)(g_k216  + ((size_t)b * N_ + m0) * 64);

#pragma unroll
    for (int it = 0; it < 4; it++) {           // q: 128 rows x 8 chunks, hi+lo
        int idx = t + 256 * it;
        int row = idx >> 3, q = idx & 7;
        uint32_t d = sbase + (uint32_t)(row * 144 + q * 16);
        int srco = row * 128 + q * 16;
        CP_ASYNC16(d + QK_QHI_B, qh + srco);
        CP_ASYNC16(d + QK_QLO_B, ql + srco);
    }
#pragma unroll
    for (int it = 0; it < 2; it++) {           // k1/k2: 64 rows x 8 chunks
        int idx = t + 256 * it;
        int row = idx >> 3, q = idx & 7;
        uint32_t d = sbase + (uint32_t)(row * 144 + q * 16);
        int srco = row * 128 + q * 16;
        CP_ASYNC16(d + QK_K1_B, k1 + srco);
        CP_ASYNC16(d + QK_K2_B, k2 + srco);
    }
    CP_ASYNC_COMMIT();
    CP_ASYNC_WAIT0();
    __syncthreads();

    const int g    = lane >> 3;
    const int arow = wn * 32 + ((g & 1) ? 8 : 0) + (lane & 7);
    const int koff = (g >> 1) * 8;
    const int brow = wm * 32 + ((g & 1) ? 8 : 0) + (lane & 7);

    float acc1[2][4][4] = {}, acc2[2][4][4] = {};

#pragma unroll
    for (int kk = 0; kk < 4; kk++) {
        uint32_t ah[2][4], al[2][4];
#pragma unroll
        for (int mi = 0; mi < 2; mi++) {
            uint32_t ka = (uint32_t)((arow + mi * 16) * 144 + (kk * 16 + koff) * 2);
            LDMATRIX_X4(ah[mi][0], ah[mi][1], ah[mi][2], ah[mi][3], sbase + QK_QHI_B + ka);
            LDMATRIX_X4(al[mi][0], al[mi][1], al[mi][2], al[mi][3], sbase + QK_QLO_B + ka);
        }
#pragma unroll
        for (int j2 = 0; j2 < 2; j2++) {
            uint32_t kb = (uint32_t)((brow + j2 * 16) * 144 + (kk * 16 + koff) * 2);
            uint32_t b1[2][2], b2[2][2];
            {
                uint32_t r0, r1, r2, r3;
                LDMATRIX_X4(r0, r1, r2, r3, sbase + QK_K1_B + kb);
                b1[0][0] = r0; b1[0][1] = r2; b1[1][0] = r1; b1[1][1] = r3;
                LDMATRIX_X4(r0, r1, r2, r3, sbase + QK_K2_B + kb);
                b2[0][0] = r0; b2[0][1] = r2; b2[1][0] = r1; b2[1][1] = r3;
            }
#pragma unroll
            for (int mi = 0; mi < 2; mi++)
#pragma unroll
                for (int jj = 0; jj < 2; jj++) {
                    int j = j2 * 2 + jj;
                    MMA_F16(acc1[mi][j], ah[mi], b1[jj]);
                    MMA_F16(acc1[mi][j], al[mi], b1[jj]);
                    MMA_F16(acc2[mi][j], ah[mi], b2[jj]);
                    MMA_F16(acc2[mi][j], al[mi], b2[jj]);
                }
        }
    }

    // ---- epilogue: exp -> smem tiles (reuse Q/K space) -> coalesced st.cs ----
    __syncthreads();
    const int gid = lane >> 2, tig = lane & 3;
#pragma unroll
    for (int mi = 0; mi < 2; mi++)
#pragma unroll
        for (int rr = 0; rr < 2; rr++) {
            int nl = wn * 32 + mi * 16 + gid + rr * 8;
#pragma unroll
            for (int j = 0; j < 4; j++) {
                int ml = wm * 32 + j * 8 + tig * 2;
                __nv_bfloat162 e1p, e2p;
                e1p.x = __float2bfloat16(__expf(acc1[mi][j][rr * 2 + 0]));
                e1p.y = __float2bfloat16(__expf(acc1[mi][j][rr * 2 + 1]));
                e2p.x = __float2bfloat16(__expf(acc2[mi][j][rr * 2 + 0]));
                e2p.y = __float2bfloat16(__expf(acc2[mi][j][rr * 2 + 1]));
                *(__nv_bfloat162*)(smem + nl * 144 + ml * 2)              = e1p;
                *(__nv_bfloat162*)(smem + 128 * 144 + nl * 144 + ml * 2)  = e2p;
            }
        }
    __syncthreads();

#pragma unroll
    for (int it = 0; it < 4; it++) {
        int idx = t + 256 * it;
        int r = idx >> 3, q = idx & 7;
        size_t goff = ((size_t)b * N_ + n0 + r) * N_ + m0 + q * 8;
        float4 v1 = *(const float4*)(smem + r * 144 + q * 16);
        __stcs((float4*)&g_attn16[goff], v1);
        float4 v2 = *(const float4*)(smem + 128 * 144 + r * 144 + q * 16);
        __stcs((float4*)&g_E2bf[goff], v2);
    }
}

// ---------------------------------------------------------------------------
// Double softmax, 256 threads, rows held in REGISTERS (4 uint4/thread),
// warp-shuffle reductions. Writes unnormalized e (fp16) in place + S -> g_S.
// ---------------------------------------------------------------------------
__global__ void __launch_bounds__(256)
softmax2_kernel()
{
    __shared__ float2 redw[8];
    __shared__ float2 bc;
    __shared__ float redS[8];
    const int b = blockIdx.y, n = blockIdx.x, t = threadIdx.x;
    const int wid = t >> 5, lane = t & 31;
    __nv_bfloat16* rowe1 = g_attn16 + ((size_t)b * N_ + n) * N_;
    const __nv_bfloat16* rowe2 = g_E2bf + ((size_t)b * N_ + n) * N_;

    const uint4* e1v = (const uint4*)rowe1;
    const uint4* e2v = (const uint4*)rowe2;

    uint4 a0 = __ldcs(&e1v[t]);
    uint4 a1 = __ldcs(&e1v[t + 256]);
    uint4 c0 = __ldcs(&e2v[t]);
    uint4 c1 = __ldcs(&e2v[t + 256]);
    float s1 = sum_bf2(a0.x) + sum_bf2(a0.y) + sum_bf2(a0.z) + sum_bf2(a0.w)
             + sum_bf2(a1.x) + sum_bf2(a1.y) + sum_bf2(a1.z) + sum_bf2(a1.w);
    float s2 = sum_bf2(c0.x) + sum_bf2(c0.y) + sum_bf2(c0.z) + sum_bf2(c0.w)
             + sum_bf2(c1.x) + sum_bf2(c1.y) + sum_bf2(c1.z) + sum_bf2(c1.w);

#pragma unroll
    for (int off = 16; off > 0; off >>= 1) {
        s1 += __shfl_xor_sync(0xffffffff, s1, off);
        s2 += __shfl_xor_sync(0xffffffff, s2, off);
    }
    if (lane == 0) redw[wid] = make_float2(s1, s2);
    __syncthreads();
    if (wid == 0) {
        float2 v = (lane < 8) ? redw[lane] : make_float2(0.f, 0.f);
#pragma unroll
        for (int off = 4; off > 0; off >>= 1) {
            v.x += __shfl_xor_sync(0xffffffff, v.x, off);
            v.y += __shfl_xor_sync(0xffffffff, v.y, off);
        }
        if (lane == 0) bc = v;
    }
    __syncthreads();
    const float i1 = 1.f / bc.x, i2 = 1.f / bc.y;

    float e[16];
    {
        float2 fa, fc;
        fa = unpk(a0.x); fc = unpk(c0.x);
        e[0] = __expf(fa.x * i1 + fc.x * i2);  e[1] = __expf(fa.y * i1 + fc.y * i2);
        fa = unpk(a0.y); fc = unpk(c0.y);
        e[2] = __expf(fa.x * i1 + fc.x * i2);  e[3] = __expf(fa.y * i1 + fc.y * i2);
        fa = unpk(a0.z); fc = unpk(c0.z);
        e[4] = __expf(fa.x * i1 + fc.x * i2);  e[5] = __expf(fa.y * i1 + fc.y * i2);
        fa = unpk(a0.w); fc = unpk(c0.w);
        e[6] = __expf(fa.x * i1 + fc.x * i2);  e[7] = __expf(fa.y * i1 + fc.y * i2);
        fa = unpk(a1.x); fc = unpk(c1.x);
        e[8] = __expf(fa.x * i1 + fc.x * i2);  e[9] = __expf(fa.y * i1 + fc.y * i2);
        fa = unpk(a1.y); fc = unpk(c1.y);
        e[10] = __expf(fa.x * i1 + fc.x * i2); e[11] = __expf(fa.y * i1 + fc.y * i2);
        fa = unpk(a1.z); fc = unpk(c1.z);
        e[12] = __expf(fa.x * i1 + fc.x * i2); e[13] = __expf(fa.y * i1 + fc.y * i2);
        fa = unpk(a1.w); fc = unpk(c1.w);
        e[14] = __expf(fa.x * i1 + fc.x * i2); e[15] = __expf(fa.y * i1 + fc.y * i2);
    }
    uint4 pk;
    __half2 p;
    p.x = __float2half(e[0]);  p.y = __float2half(e[1]);  pk.x = *(uint32_t*)&p;
    p.x = __float2half(e[2]);  p.y = __float2half(e[3]);  pk.y = *(uint32_t*)&p;
    p.x = __float2half(e[4]);  p.y = __float2half(e[5]);  pk.z = *(uint32_t*)&p;
    p.x = __float2half(e[6]);  p.y = __float2half(e[7]);  pk.w = *(uint32_t*)&p;
    ((uint4*)rowe1)[t] = pk;
    p.x = __float2half(e[8]);  p.y = __float2half(e[9]);  pk.x = *(uint32_t*)&p;
    p.x = __float2half(e[10]); p.y = __float2half(e[11]); pk.y = *(uint32_t*)&p;
    p.x = __float2half(e[12]); p.y = __float2half(e[13]); pk.z = *(uint32_t*)&p;
    p.x = __float2half(e[14]); p.y = __float2half(e[15]); pk.w = *(uint32_t*)&p;
    ((uint4*)rowe1)[t + 256] = pk;

    float s = 0.f;
#pragma unroll
    for (int i = 0; i < 16; i++) s += e[i];
#pragma unroll
    for (int off = 16; off > 0; off >>= 1)
        s += __shfl_xor_sync(0xffffffff, s, off);
    if (lane == 0) redS[wid] = s;
    __syncthreads();
    if (wid == 0) {
        float v = (lane < 8) ? redS[lane] : 0.f;
#pragma unroll
        for (int off = 4; off > 0; off >>= 1)
            v += __shfl_xor_sync(0xffffffff, v, off);
        if (lane == 0) g_S[(size_t)b * N_ + n] = v;
    }
}

// ---------------------------------------------------------------------------
// Expand: fp16 e -> fp32 attn = e / S[row]. Runs concurrent with AV.
// ---------------------------------------------------------------------------
__global__ void expand_kernel(float* __restrict__ attn)
{
    const int b = blockIdx.y, n = blockIdx.x, t = threadIdx.x;
    const __half* rowh = (const __half*)(g_attn16 + ((size_t)b * N_ + n) * N_);
    float* rowf = attn + ((size_t)b * N_ + n) * N_;
    const float ds = 1.f / g_S[(size_t)b * N_ + n];
#pragma unroll
    for (int i = 0; i < 2; i++) {
        int ci = t + 256 * i;
        uint4 h = __ldcs(&((const uint4*)rowh)[ci]);
        float2 f0 = __half22float2(*(__half2*)&h.x);
        float2 f1 = __half22float2(*(__half2*)&h.y);
        float2 f2 = __half22float2(*(__half2*)&h.z);
        float2 f3 = __half22float2(*(__half2*)&h.w);
        float4 o0, o1;
        o0.x = f0.x * ds; o0.y = f0.y * ds; o0.z = f1.x * ds; o0.w = f1.y * ds;
        o1.x = f2.x * ds; o1.y = f2.y * ds; o1.z = f3.x * ds; o1.w = f3.y * ds;
        __stcs((float4*)&rowf[ci * 8],     o0);
        __stcs((float4*)&rowf[ci * 8 + 4], o1);
    }
}

// ---------------------------------------------------------------------------
// AV dual GEMM on mma.sync fp16 over unnormalized e; epilogue applies
// gamma * acc / S[n] + x residual. 128c x 128n, 512 thr, 3-stage cp.async.
// ---------------------------------------------------------------------------
#define AV_VOFF_B   0
#define AV_WOFF_B   (128 * 144)
#define AV_AOFF_B   (256 * 144)
#define AV_STAGE_B  (384 * 144)          // 55296 B per stage
#define AV_SMEM_TOTAL (3 * AV_STAGE_B)   // 165888 B

__device__ __forceinline__ void av_issue(uint32_t sb, const __half* gv,
                                         const __half* gw, const __half* ga,
                                         int m0, int t)
{
#pragma unroll
    for (int it = 0; it < 2; it++) {
        int idx = t + 512 * it;
        int row = idx >> 3, q = idx & 7;
        uint32_t d = sb + (uint32_t)(row * 144 + q * 16);
        CP_ASYNC16(d + AV_VOFF_B, (const char*)(gv + (size_t)row * N_ + m0) + q * 16);
        CP_ASYNC16(d + AV_WOFF_B, (const char*)(gw + (size_t)row * N_ + m0) + q * 16);
        CP_ASYNC16(d + AV_AOFF_B, (const char*)(ga + (size_t)row * N_ + m0) + q * 16);
    }
}

__global__ void __launch_bounds__(512, 1)
av_mma_kernel(const float* __restrict__ x3, const float* __restrict__ xt,
              const float* __restrict__ gma, const float* __restrict__ gma2,
              float* __restrict__ out1, float* __restrict__ out2)
{
    extern __shared__ __align__(16) char smem[];
    const uint32_t sbase = smem_u32(smem);
    const int t = threadIdx.x;
    const int wid = t / 32, lane = t % 32;
    const int wc = wid >> 2, wn = wid & 3;

    const int b  = blockIdx.z;
    const int c0 = blockIdx.y * 128;
    const int n0 = blockIdx.x * 128;

    const __half* vb = g_vhf  + ((size_t)b * C_ + c0) * N_;
    const __half* wb = g_vthf + ((size_t)b * C_ + c0) * N_;
    const __half* ab = (const __half*)g_attn16 + ((size_t)b * N_ + n0) * N_;

    float acc1[2][4][4] = {}, acc2[2][4][4] = {};

    const int g      = lane >> 3;
    const int arow   = wc * 32 + ((g & 1) ? 8 : 0) + (lane & 7);
    const int akoff  = (g >> 1) * 8;
    const int brow   = wn * 32 + ((g & 1) ? 8 : 0) + (lane & 7);
    const int bkoff  = (g >> 1) * 8;

    av_issue(sbase + 0 * AV_STAGE_B, vb, wb, ab, 0,  t); CP_ASYNC_COMMIT();
    av_issue(sbase + 1 * AV_STAGE_B, vb, wb, ab, 64, t); CP_ASYNC_COMMIT();

    int stage = 0;
    for (int i = 0; i < 64; i++) {
        if (i + 2 < 64) {
            int s2 = stage + 2; if (s2 >= 3) s2 -= 3;
            av_issue(sbase + s2 * AV_STAGE_B, vb, wb, ab, (i + 2) * 64, t);
            CP_ASYNC_COMMIT();
            CP_ASYNC_WAIT2();
        } else if (i + 1 < 64) {
            CP_ASYNC_WAIT1();
        } else {
            CP_ASYNC_WAIT0();
        }
        __syncthreads();

        const uint32_t st = sbase + stage * AV_STAGE_B;
#pragma unroll
        for (int kk = 0; kk < 4; kk++) {
            uint32_t av[2][4], aw[2][4], bfr[4][2];
#pragma unroll
            for (int mi = 0; mi < 2; mi++) {
                uint32_t roff = (uint32_t)((arow + mi * 16) * 144 + (kk * 16 + akoff) * 2);
                LDMATRIX_X4(av[mi][0], av[mi][1], av[mi][2], av[mi][3], st + AV_VOFF_B + roff);
                LDMATRIX_X4(aw[mi][0], aw[mi][1], aw[mi][2], aw[mi][3], st + AV_WOFF_B + roff);
            }
#pragma unroll
            for (int j2 = 0; j2 < 2; j2++) {
                uint32_t r0, r1, r2, r3;
                uint32_t baddr = st + AV_AOFF_B +
                    (uint32_t)((brow + j2 * 16) * 144 + (kk * 16 + bkoff) * 2);
                LDMATRIX_X4(r0, r1, r2, r3, baddr);
                bfr[j2 * 2 + 0][0] = r0; bfr[j2 * 2 + 0][1] = r2;
                bfr[j2 * 2 + 1][0] = r1; bfr[j2 * 2 + 1][1] = r3;
            }
#pragma unroll
            for (int mi = 0; mi < 2; mi++)
#pragma unroll
                for (int j = 0; j < 4; j++) {
                    MMA_F16(acc1[mi][j], av[mi], bfr[j]);
                    MMA_F16(acc2[mi][j], aw[mi], bfr[j]);
                }
        }
        __syncthreads();
        if (++stage == 3) stage = 0;
    }

    const float gv1 = gma[0], gv2 = gma2[0];
    const float* Sb = g_S + (size_t)b * N_;
    const int gid = lane >> 2, tig = lane & 3;
#pragma unroll
    for (int mi = 0; mi < 2; mi++) {
#pragma unroll
        for (int rr = 0; rr < 2; rr++) {
            int c = c0 + wc * 32 + mi * 16 + gid + rr * 8;
            size_t rowoff = ((size_t)b * C_ + c) * N_;
#pragma unroll
            for (int j = 0; j < 4; j++) {
                int n = n0 + wn * 32 + j * 8 + tig * 2;
                float2 Sv = *(const float2*)&Sb[n];
                float r1s = gv1 / Sv.x, r1s2 = gv1 / Sv.y;
                float r2s = gv2 / Sv.x, r2s2 = gv2 / Sv.y;
                float2 xv = *(const float2*)&x3[rowoff + n];
                float2 o1;
                o1.x = r1s  * acc1[mi][j][rr * 2 + 0] + xv.x;
                o1.y = r1s2 * acc1[mi][j][rr * 2 + 1] + xv.y;
                *(float2*)&out1[rowoff + n] = o1;
                float2 xtv = *(const float2*)&xt[rowoff + n];
                float2 o2;
                o2.x = r2s  * acc2[mi][j][rr * 2 + 0] + xtv.x;
                o2.y = r2s2 * acc2[mi][j][rr * 2 + 1] + xtv.y;
                *(float2*)&out2[rowoff + n] = o2;
            }
        }
    }
}

// ---------------------------------------------------------------------------
extern "C" void kernel_launch(void* const* d_in, const int* in_sizes, int n_in,
                              void* d_out, int out_size)
{
    const float* x1  = (const float*)d_in[0];
    const float* x2  = (const float*)d_in[1];
    const float* x3  = (const float*)d_in[2];
    const float* xt  = (const float*)d_in[3];
    const float* Wq  = (const float*)d_in[4];
    const float* bq  = (const float*)d_in[5];
    const float* Wk  = (const float*)d_in[6];
    const float* bk  = (const float*)d_in[7];
    const float* Wk2 = (const float*)d_in[8];
    const float* bk2 = (const float*)d_in[9];
    const float* Wv  = (const float*)d_in[10];
    const float* bv  = (const float*)d_in[11];
    const float* Wv2 = (const float*)d_in[12];
    const float* bv2 = (const float*)d_in[13];
    const float* gamma  = (const float*)d_in[14];
    const float* gamma2 = (const float*)d_in[15];

    float* attn = (float*)d_out;
    float* out1 = attn + ATTN_ELEMS;
    float* out2 = out1 + OUT_ELEMS;

    // Streams/events created once (host-side resources only).
    static cudaStream_t sv = nullptr;   // side stream: proj_v, then expand
    static cudaEvent_t ev_fork = nullptr, ev_vdone = nullptr;
    static cudaEvent_t ev_smdone = nullptr, ev_expdone = nullptr;
    if (sv == nullptr) {
        cudaStreamCreateWithFlags(&sv, cudaStreamNonBlocking);
        cudaEventCreateWithFlags(&ev_fork, cudaEventDisableTiming);
        cudaEventCreateWithFlags(&ev_vdone, cudaEventDisableTiming);
        cudaEventCreateWithFlags(&ev_smdone, cudaEventDisableTiming);
        cudaEventCreateWithFlags(&ev_expdone, cudaEventDisableTiming);
    }

    dim3 blk(256);

    // fork: v/vt projections on side stream (needed only by AV)
    cudaEventRecord(ev_fork, 0);
    cudaStreamWaitEvent(sv, ev_fork, 0);
    proj_v2_kernel<<<dim3(N_ / 64, C_ / 64, 2 * B_), blk, 0, sv>>>(Wv, bv, Wv2, bv2, x3, xt);
    cudaEventRecord(ev_vdone, sv);

    // main chain: fused q/k projections -> QK -> softmax
    proj_qk3_kernel<<<dim3(N_ / 64, 3, B_), blk>>>(Wq, bq, Wk, bk, Wk2, bk2, x3, x1, x2);

    cudaFuncSetAttribute(qk_mma_kernel, cudaFuncAttributeMaxDynamicSharedMemorySize, QK_SMEM_TOTAL);
    qk_mma_kernel<<<dim3(N_ / 64, N_ / 128, B_), blk, QK_SMEM_TOTAL>>>();

    softmax2_kernel<<<dim3(N_, B_), blk>>>();
    cudaEventRecord(ev_smdone, 0);

    // expand fp32 attn on side stream, concurrent with AV (AV is tensor-bound)
    cudaStreamWaitEvent(sv, ev_smdone, 0);
    expand_kernel<<<dim3(N_, B_), blk, 0, sv>>>(attn);
    cudaEventRecord(ev_expdone, sv);

    // AV on main stream (needs softmax fp16 e + S + v/vt)
    cudaStreamWaitEvent(0, ev_vdone, 0);
    cudaFuncSetAttribute(av_mma_kernel, cudaFuncAttributeMaxDynamicSharedMemorySize, AV_SMEM_TOTAL);
    av_mma_kernel<<<dim3(N_ / 128, C_ / 128, B_), dim3(512), AV_SMEM_TOTAL>>>(
        x3, xt, gamma, gamma2, out1, out2);

    // rejoin: expand must be ordered before capture end
    cudaStreamWaitEvent(0, ev_expdone, 0);
}